// round 11
// baseline (speedup 1.0000x reference)
#include <cuda_runtime.h>
#include <cuda_bf16.h>
#include <math.h>
#include <cstdint>

// ---------------------------------------------------------------------------
// DBS_lstm: 3-layer LSTM (T=512, H=1024, batch=1) + output projection.
//   xg0  : fp32 sgemm (K=85)                      [R10 verbatim]
//   lstm : persistent kernel — 32x4 group barrier, fused bf16 split publish
//   xg1, xg2, out : split-bf16 warp-MMA GEMM      [R10 verbatim]
// ---------------------------------------------------------------------------

#define T_FRAMES 512
#define HID      1024
#define GATES    (4 * HID)
#define IN_DIM   85
#define OUT_N    (6890 * 3)
#define NCTA_LSTM 128
#define NTHR_LSTM 256

// --------------------------- scratch (device globals) ----------------------
__device__ float    g_xg[T_FRAMES * GATES];
__device__ float4   g_h4[HID / 4];
__device__ unsigned g_cnt1[32 * 32];   // 32 group counters, one per 128B line

__device__ __nv_bfloat16 g_wih_h[2][GATES * HID];   // layers 1,2
__device__ __nv_bfloat16 g_wih_l[2][GATES * HID];
__device__ __nv_bfloat16 g_wout_h[OUT_N * HID];
__device__ __nv_bfloat16 g_wout_l[OUT_N * HID];
__device__ __nv_bfloat16 g_a_h[T_FRAMES * HID];
__device__ __nv_bfloat16 g_a_l[T_FRAMES * HID];

// ------------------------------ helpers -------------------------------------
__device__ __forceinline__ uint32_t smem_u32(const void* p) {
    uint32_t a;
    asm("{ .reg .u64 t; cvta.to.shared.u64 t, %1; cvt.u32.u64 %0, t; }"
        : "=r"(a) : "l"(p));
    return a;
}
__device__ __forceinline__ unsigned ld_acq_gpu(const unsigned* p) {
    unsigned v;
    asm volatile("ld.acquire.gpu.global.u32 %0, [%1];" : "=r"(v) : "l"(p));
    return v;
}
__device__ __forceinline__ unsigned atom_add_acqrel(unsigned* p, unsigned v) {
    unsigned old;
    asm volatile("atom.acq_rel.gpu.global.add.u32 %0, [%1], %2;"
                 : "=r"(old) : "l"(p), "r"(v) : "memory");
    return old;
}
__device__ __forceinline__ float fast_tanh(float x) {
    float y; asm("tanh.approx.f32 %0, %1;" : "=f"(y) : "f"(x)); return y;
}
__device__ __forceinline__ float fast_sig(float x) {
    return fmaf(0.5f, fast_tanh(0.5f * x), 0.5f);
}

#define LDSM4(r, addr)                                                        \
    asm volatile("ldmatrix.sync.aligned.m8n8.x4.shared.b16 {%0,%1,%2,%3}, [%4];" \
        : "=r"((r)[0]), "=r"((r)[1]), "=r"((r)[2]), "=r"((r)[3]) : "r"(addr))

#define MMA_BF16(c, a, b0, b1)                                                \
    asm volatile("mma.sync.aligned.m16n8k16.row.col.f32.bf16.bf16.f32 "       \
        "{%0,%1,%2,%3}, {%4,%5,%6,%7}, {%8,%9}, {%0,%1,%2,%3};"               \
        : "+f"((c)[0]), "+f"((c)[1]), "+f"((c)[2]), "+f"((c)[3])              \
        : "r"((a)[0]), "r"((a)[1]), "r"((a)[2]), "r"((a)[3]),                 \
          "r"(b0), "r"(b1))

// ===================== fp32 -> (bf16 hi, bf16 lo) convert ====================
__global__ void split_bf16_kernel(const float* __restrict__ x,
                                  __nv_bfloat16* __restrict__ hi,
                                  __nv_bfloat16* __restrict__ lo, int n)
{
    int i = blockIdx.x * blockDim.x + threadIdx.x;
    if (i < n) {
        const float v = x[i];
        const __nv_bfloat16 h = __float2bfloat16(v);
        hi[i] = h;
        lo[i] = __float2bfloat16(v - __bfloat162float(h));
    }
}

// ============ split-bf16 warp-MMA GEMM (R10 verbatim) =======================
#define WBM 64
#define WBN 128
#define WKC 32
#define APITCH 80
#define OFF_AH 0
#define OFF_AL (OFF_AH + WBM * APITCH)
#define OFF_BH (OFF_AL + WBM * APITCH)
#define OFF_BL (OFF_BH + WBN * APITCH)
#define SMEM_SZ (OFF_BL + WBN * APITCH)

__global__ __launch_bounds__(256)
void bf16mma_gemm(const __nv_bfloat16* __restrict__ Ah,
                  const __nv_bfloat16* __restrict__ Al,
                  const __nv_bfloat16* __restrict__ Bh,
                  const __nv_bfloat16* __restrict__ Bl,
                  const float* __restrict__ b0, const float* __restrict__ b1,
                  float* __restrict__ C, int M, int N, int K)
{
    __shared__ __align__(128) char smem[SMEM_SZ];
    const uint32_t sbase = smem_u32(smem);

    const int tid  = threadIdx.x;
    const int lane = tid & 31;
    const int w    = tid >> 5;
    const int mrow = w & 1;
    const int ncol = w >> 1;
    const int m0   = blockIdx.y * WBM;
    const int n0   = blockIdx.x * WBN;

    float c[2][4][4];
#pragma unroll
    for (int i = 0; i < 2; ++i)
#pragma unroll
        for (int j = 0; j < 4; ++j)
#pragma unroll
            for (int q = 0; q < 4; ++q) c[i][j][q] = 0.f;

    uint4 pah, pal, pbh0, pbl0, pbh1, pbl1;
    const int ar = tid >> 2, aj = tid & 3;
    const int br0 = tid >> 2, br1 = br0 + 64;
    const uint4 zz = make_uint4(0u, 0u, 0u, 0u);

#define GLOAD(kb)                                                             \
    {                                                                         \
        const size_t ao = (size_t)(m0 + ar) * K + (kb) + aj * 8;              \
        pah = *(const uint4*)(Ah + ao);                                       \
        pal = *(const uint4*)(Al + ao);                                       \
        const int nn0 = n0 + br0, nn1 = n0 + br1;                             \
        if (nn0 < N) {                                                        \
            const size_t bo = (size_t)nn0 * K + (kb) + aj * 8;                \
            pbh0 = *(const uint4*)(Bh + bo);                                  \
            pbl0 = *(const uint4*)(Bl + bo);                                  \
        } else { pbh0 = zz; pbl0 = zz; }                                      \
        if (nn1 < N) {                                                        \
            const size_t bo = (size_t)nn1 * K + (kb) + aj * 8;                \
            pbh1 = *(const uint4*)(Bh + bo);                                  \
            pbl1 = *(const uint4*)(Bl + bo);                                  \
        } else { pbh1 = zz; pbl1 = zz; }                                      \
    }
#define STS()                                                                 \
    {                                                                         \
        *(uint4*)(smem + OFF_AH + ar * APITCH + aj * 16) = pah;               \
        *(uint4*)(smem + OFF_AL + ar * APITCH + aj * 16) = pal;               \
        *(uint4*)(smem + OFF_BH + br0 * APITCH + aj * 16) = pbh0;             \
        *(uint4*)(smem + OFF_BL + br0 * APITCH + aj * 16) = pbl0;             \
        *(uint4*)(smem + OFF_BH + br1 * APITCH + aj * 16) = pbh1;             \
        *(uint4*)(smem + OFF_BL + br1 * APITCH + aj * 16) = pbl1;             \
    }
#define COMPUTE()                                                             \
    {                                                                         \
        _Pragma("unroll")                                                     \
        for (int ks = 0; ks < WKC; ks += 16) {                                \
            uint32_t ah[2][4], al[2][4], bh[2][4], bl[2][4];                  \
            _Pragma("unroll")                                                 \
            for (int mt = 0; mt < 2; ++mt) {                                  \
                const uint32_t arow = mrow * 32 + mt * 16 + (lane & 15);      \
                const uint32_t acol = (ks + (lane >> 4) * 8) * 2;             \
                LDSM4(ah[mt], sbase + OFF_AH + arow * APITCH + acol);         \
                LDSM4(al[mt], sbase + OFF_AL + arow * APITCH + acol);         \
            }                                                                 \
            _Pragma("unroll")                                                 \
            for (int p = 0; p < 2; ++p) {                                     \
                const uint32_t brow = ncol * 32 + p * 16 + (lane & 7)         \
                                      + ((lane >> 4) & 1) * 8;                \
                const uint32_t bcol = (ks + ((lane >> 3) & 1) * 8) * 2;       \
                LDSM4(bh[p], sbase + OFF_BH + brow * APITCH + bcol);          \
                LDSM4(bl[p], sbase + OFF_BL + brow * APITCH + bcol);          \
            }                                                                 \
            _Pragma("unroll")                                                 \
            for (int mt = 0; mt < 2; ++mt)                                    \
                _Pragma("unroll")                                             \
                for (int nt = 0; nt < 4; ++nt) {                              \
                    const int p  = nt >> 1;                                   \
                    const int r0 = (nt & 1) * 2, r1 = r0 + 1;                 \
                    MMA_BF16(c[mt][nt], ah[mt], bh[p][r0], bh[p][r1]);        \
                    MMA_BF16(c[mt][nt], ah[mt], bl[p][r0], bl[p][r1]);        \
                    MMA_BF16(c[mt][nt], al[mt], bh[p][r0], bh[p][r1]);        \
                }                                                             \
        }                                                                     \
    }

    GLOAD(0);
    STS();
    __syncthreads();

    for (int kb = WKC; kb < K; kb += WKC) {
        GLOAD(kb);
        COMPUTE();
        __syncthreads();
        STS();
        __syncthreads();
    }
    COMPUTE();

#pragma unroll
    for (int mt = 0; mt < 2; ++mt) {
        const int mbase = m0 + mrow * 32 + mt * 16 + (lane >> 2);
#pragma unroll
        for (int nt = 0; nt < 4; ++nt) {
            const int n = n0 + ncol * 32 + nt * 8 + (lane & 3) * 2;
#pragma unroll
            for (int half = 0; half < 2; ++half) {
                const int m = mbase + half * 8;
                const float v0 = c[mt][nt][half * 2 + 0];
                const float v1 = c[mt][nt][half * 2 + 1];
                if (n < N) {
                    float v = v0;
                    if (b0) v += __ldg(&b0[n]);
                    if (b1) v += __ldg(&b1[n]);
                    C[(size_t)m * N + n] = v;
                }
                if (n + 1 < N) {
                    float v = v1;
                    if (b0) v += __ldg(&b0[n + 1]);
                    if (b1) v += __ldg(&b1[n + 1]);
                    C[(size_t)m * N + n + 1] = v;
                }
            }
        }
    }
#undef GLOAD
#undef STS
#undef COMPUTE
}

// =================== fp32 SGEMM (layer-0 xg, R10 verbatim) ==================
#define BM 64
#define BN 64
#define BK 16

__global__ __launch_bounds__(256)
void sgemm_nt_kernel(const float* __restrict__ A, const float* __restrict__ B,
                     const float* __restrict__ b0, const float* __restrict__ b1,
                     float* __restrict__ C, int M, int N, int K)
{
    __shared__ float As[BK][68];
    __shared__ float Bs[BK][68];

    const int tid = threadIdx.x;
    const int tx  = tid & 15;
    const int ty  = tid >> 4;
    const int lk  = tid & 15;
    const int lr  = tid >> 4;
    const int m0 = blockIdx.y * BM;
    const int n0 = blockIdx.x * BN;

    float acc[4][4];
#pragma unroll
    for (int i = 0; i < 4; ++i)
#pragma unroll
        for (int j = 0; j < 4; ++j) acc[i][j] = 0.f;

    for (int k0 = 0; k0 < K; k0 += BK) {
        const int k = k0 + lk;
        const bool kok = (k < K);
#pragma unroll
        for (int i = 0; i < 4; ++i) {
            const int m = m0 + lr + 16 * i;
            const int n = n0 + lr + 16 * i;
            As[lk][lr + 16 * i] = (kok && m < M) ? __ldg(&A[(size_t)m * K + k]) : 0.f;
            Bs[lk][lr + 16 * i] = (kok && n < N) ? __ldg(&B[(size_t)n * K + k]) : 0.f;
        }
        __syncthreads();
#pragma unroll
        for (int kk = 0; kk < BK; ++kk) {
            const float4 a = *(const float4*)&As[kk][ty * 4];
            const float4 b = *(const float4*)&Bs[kk][tx * 4];
            acc[0][0] = fmaf(a.x, b.x, acc[0][0]);
            acc[0][1] = fmaf(a.x, b.y, acc[0][1]);
            acc[0][2] = fmaf(a.x, b.z, acc[0][2]);
            acc[0][3] = fmaf(a.x, b.w, acc[0][3]);
            acc[1][0] = fmaf(a.y, b.x, acc[1][0]);
            acc[1][1] = fmaf(a.y, b.y, acc[1][1]);
            acc[1][2] = fmaf(a.y, b.z, acc[1][2]);
            acc[1][3] = fmaf(a.y, b.w, acc[1][3]);
            acc[2][0] = fmaf(a.z, b.x, acc[2][0]);
            acc[2][1] = fmaf(a.z, b.y, acc[2][1]);
            acc[2][2] = fmaf(a.z, b.z, acc[2][2]);
            acc[2][3] = fmaf(a.z, b.w, acc[2][3]);
            acc[3][0] = fmaf(a.w, b.x, acc[3][0]);
            acc[3][1] = fmaf(a.w, b.y, acc[3][1]);
            acc[3][2] = fmaf(a.w, b.z, acc[3][2]);
            acc[3][3] = fmaf(a.w, b.w, acc[3][3]);
        }
        __syncthreads();
    }

#pragma unroll
    for (int i = 0; i < 4; ++i) {
        const int m = m0 + ty * 4 + i;
        if (m >= M) continue;
#pragma unroll
        for (int j = 0; j < 4; ++j) {
            const int n = n0 + tx * 4 + j;
            if (n >= N) continue;
            float v = acc[i][j];
            if (b0) v += __ldg(&b0[n]);
            if (b1) v += __ldg(&b1[n]);
            C[(size_t)m * N + n] = v;
        }
    }
}

// =================== persistent LSTM recurrence ==============================
// 128 CTAs (1/SM), 256 threads. Warp w owns hidden unit (cta*8 + w); gate =
// lane>>3, 128 weights/lane in registers, in-warp gate gather (R10 structure).
// Barrier: 32 groups of 4 CTAs (arrival convoy 4 deep, not 16); warp0's 32
// lanes each poll exactly one counter line. Publish fuses the bf16 hi/lo
// split of h (feeds the tensor GEMMs directly — no separate split kernels).

__global__ __launch_bounds__(NTHR_LSTM, 1)
void lstm_layer_kernel(const float* __restrict__ Whh,
                       const float* __restrict__ xg,
                       __nv_bfloat16* __restrict__ ah_out,   // [512,1024] bf16 hi
                       __nv_bfloat16* __restrict__ al_out)   // [512,1024] bf16 lo
{
    __shared__ float4 hs4[HID / 4];

    const int tid   = threadIdx.x;
    const int cta   = blockIdx.x;
    const int base  = cta * 8;
    const int lane  = tid & 31;
    const int warp  = tid >> 5;        // unit within CTA
    const int gate  = lane >> 3;       // 0..3 = i,f,g,o
    const int lane8 = lane & 7;

    // Stage 128 weights/thread into registers (row = gate*HID + base + warp).
    const float4* wsrc =
        (const float4*)(Whh + (size_t)(gate * HID + base + warp) * HID);
    float4 wr[32];
#pragma unroll
    for (int jj = 0; jj < 32; ++jj)
        wr[jj] = __ldg(&wsrc[lane8 + 8 * jj]);

    hs4[tid] = make_float4(0.f, 0.f, 0.f, 0.f);

    // Per-lane group-counter base (warp 0, all 32 lanes). Counters gain
    // exactly 2048 per launch; <= +3 drift before snapshot -> mask exact.
    unsigned baseg = 0;
    if (warp == 0)
        baseg = ld_acq_gpu(&g_cnt1[lane * 32]) & ~2047u;

    const int gate_off = gate * HID + base + warp;
    float xgv = 0.f;
    if (lane8 == 0) xgv = __ldg(xg + gate_off);
    float c_reg = 0.f;
    __syncthreads();

    for (int t = 0; t < T_FRAMES; ++t) {
        // ---- dot: 128 weights x h ----
        float sum = 0.f;
#pragma unroll
        for (int jj = 0; jj < 32; ++jj) {
            const float4 h = hs4[lane8 + 8 * jj];
            sum = fmaf(wr[jj].x, h.x, sum);
            sum = fmaf(wr[jj].y, h.y, sum);
            sum = fmaf(wr[jj].z, h.z, sum);
            sum = fmaf(wr[jj].w, h.w, sum);
        }
        sum += __shfl_xor_sync(0xffffffffu, sum, 1);
        sum += __shfl_xor_sync(0xffffffffu, sum, 2);
        sum += __shfl_xor_sync(0xffffffffu, sum, 4);

        // activations on the 4 gate leaders (lanes 0,8,16,24)
        float act = 0.f;
        if (lane8 == 0) {
            const float a = sum + xgv;
            act = (gate == 2) ? fast_tanh(a) : fast_sig(a);
        }
        // prefetch next xg (independent; hides LDG under the barrier wait)
        float xgn = 0.f;
        if (lane8 == 0 && t + 1 < T_FRAMES)
            xgn = __ldg(xg + (size_t)(t + 1) * GATES + gate_off);

        // ---- in-warp gate gather + cell/hidden update ----
        const float i_ = __shfl_sync(0xffffffffu, act, 0);
        const float f_ = __shfl_sync(0xffffffffu, act, 8);
        const float g_ = __shfl_sync(0xffffffffu, act, 16);
        const float o_ = __shfl_sync(0xffffffffu, act, 24);
        c_reg = f_ * c_reg + i_ * g_;               // identical in all lanes
        const float h = o_ * fast_tanh(c_reg);
        if (lane == 0) {
            __stcg(((float*)g_h4) + base + warp, h);
            // fused bf16 hi/lo split (consumed by the tensor GEMMs)
            const __nv_bfloat16 hh = __float2bfloat16(h);
            ah_out[(size_t)t * HID + base + warp] = hh;
            al_out[(size_t)t * HID + base + warp] =
                __float2bfloat16(h - __bfloat162float(hh));
        }

        // ---- producer/consumer barrier split ----
        if (warp != 0) {
            asm volatile("bar.arrive 1, %0;" :: "r"(NTHR_LSTM) : "memory");
        } else {
            asm volatile("bar.sync 1, %0;" :: "r"(NTHR_LSTM) : "memory");
            // all warps' h stores are now ordered before the release atom
            if (lane == 0) {
                asm volatile("fence.acq_rel.gpu;" ::: "memory");
                atom_add_acqrel(&g_cnt1[(cta >> 2) * 32], 1u);
            }
            if (t < T_FRAMES - 1) {
                // each lane watches one group counter
                const unsigned tgt = baseg + 4u * (unsigned)(t + 1);
                bool ok;
                do {
                    ok = ((int)(ld_acq_gpu(&g_cnt1[lane * 32]) - tgt) >= 0);
                } while (!__all_sync(0xffffffffu, ok));
            }
        }

        if (t == T_FRAMES - 1) break;

        __syncthreads();                       // wait complete for all warps
        hs4[tid] = __ldcg(((const float4*)g_h4) + tid);
        xgv = xgn;
        __syncthreads();                       // hs4 ready for next dot
    }
}

// ================================ launch =====================================
extern "C" void kernel_launch(void* const* d_in, const int* in_sizes, int n_in,
                              void* d_out, int out_size)
{
    (void)in_sizes; (void)n_in; (void)out_size;

    const float* x       = (const float*)d_in[0];
    const float* W_ih[3] = {(const float*)d_in[1], (const float*)d_in[5], (const float*)d_in[9]};
    const float* W_hh[3] = {(const float*)d_in[2], (const float*)d_in[6], (const float*)d_in[10]};
    const float* b_ih[3] = {(const float*)d_in[3], (const float*)d_in[7], (const float*)d_in[11]};
    const float* b_hh[3] = {(const float*)d_in[4], (const float*)d_in[8], (const float*)d_in[12]};
    const float* W_out   = (const float*)d_in[13];
    float* out = (float*)d_out;

    float* xg;
    __nv_bfloat16 *wih_h, *wih_l, *wout_h, *wout_l, *a_h, *a_l;
    cudaGetSymbolAddress((void**)&xg,     g_xg);
    cudaGetSymbolAddress((void**)&wih_h,  g_wih_h);
    cudaGetSymbolAddress((void**)&wih_l,  g_wih_l);
    cudaGetSymbolAddress((void**)&wout_h, g_wout_h);
    cudaGetSymbolAddress((void**)&wout_l, g_wout_l);
    cudaGetSymbolAddress((void**)&a_h,    g_a_h);
    cudaGetSymbolAddress((void**)&a_l,    g_a_l);

    const dim3 blk256(256);
    const int  WIH_ELEMS  = GATES * HID;
    const int  WOUT_ELEMS = OUT_N * HID;

    // ---- weight conversions (pure functions of inputs) ----
    split_bf16_kernel<<<(WIH_ELEMS + 255) / 256, blk256>>>(W_ih[1], wih_h, wih_l, WIH_ELEMS);
    split_bf16_kernel<<<(WIH_ELEMS + 255) / 256, blk256>>>(W_ih[2], wih_h + WIH_ELEMS,
                                                           wih_l + WIH_ELEMS, WIH_ELEMS);
    split_bf16_kernel<<<(WOUT_ELEMS + 255) / 256, blk256>>>(W_out, wout_h, wout_l, WOUT_ELEMS);

    // ---- layer 0: fp32 xg GEMM (K=85) + recurrence ----
    const dim3 grid_xg0(GATES / BN, T_FRAMES / BM);            // (64, 8)
    sgemm_nt_kernel<<<grid_xg0, blk256>>>(x, W_ih[0], b_ih[0], b_hh[0], xg,
                                          T_FRAMES, GATES, IN_DIM);
    lstm_layer_kernel<<<NCTA_LSTM, blk256>>>(W_hh[0], xg, a_h, a_l);

    // ---- layer 1 ----
    const dim3 grid_xgt(GATES / WBN, T_FRAMES / WBM);          // (32, 8)
    bf16mma_gemm<<<grid_xgt, blk256>>>(a_h, a_l, wih_h, wih_l,
                                       b_ih[1], b_hh[1], xg,
                                       T_FRAMES, GATES, HID);
    lstm_layer_kernel<<<NCTA_LSTM, blk256>>>(W_hh[1], xg, a_h, a_l);

    // ---- layer 2 ----
    bf16mma_gemm<<<grid_xgt, blk256>>>(a_h, a_l, wih_h + WIH_ELEMS,
                                       wih_l + WIH_ELEMS,
                                       b_ih[2], b_hh[2], xg,
                                       T_FRAMES, GATES, HID);
    lstm_layer_kernel<<<NCTA_LSTM, blk256>>>(W_hh[2], xg, a_h, a_l);

    // ---- output projection ----
    const dim3 grid_out((OUT_N + WBN - 1) / WBN, T_FRAMES / WBM);  // (162, 8)
    bf16mma_gemm<<<grid_out, blk256>>>(a_h, a_l, wout_h, wout_l,
                                       nullptr, nullptr, out,
                                       T_FRAMES, OUT_N, HID);
}

// round 12
// speedup vs baseline: 1.0119x; 1.0119x over previous
#include <cuda_runtime.h>
#include <cuda_bf16.h>
#include <math.h>
#include <cstdint>

// ---------------------------------------------------------------------------
// DBS_lstm: 3-layer LSTM (T=512, H=1024, batch=1) + output projection.
//   xg0  : fp32 sgemm (K=85)                      [R11 verbatim]
//   lstm : persistent kernel                      [R11 verbatim]
//   xg1, xg2, out : split-bf16 warp-MMA GEMM — NOW cp.async double-buffered
// ---------------------------------------------------------------------------

#define T_FRAMES 512
#define HID      1024
#define GATES    (4 * HID)
#define IN_DIM   85
#define OUT_N    (6890 * 3)
#define NCTA_LSTM 128
#define NTHR_LSTM 256

// --------------------------- scratch (device globals) ----------------------
__device__ float    g_xg[T_FRAMES * GATES];
__device__ float4   g_h4[HID / 4];
__device__ unsigned g_cnt1[32 * 32];   // 32 group counters, one per 128B line

__device__ __nv_bfloat16 g_wih_h[2][GATES * HID];   // layers 1,2
__device__ __nv_bfloat16 g_wih_l[2][GATES * HID];
__device__ __nv_bfloat16 g_wout_h[OUT_N * HID];
__device__ __nv_bfloat16 g_wout_l[OUT_N * HID];
__device__ __nv_bfloat16 g_a_h[T_FRAMES * HID];
__device__ __nv_bfloat16 g_a_l[T_FRAMES * HID];

// ------------------------------ helpers -------------------------------------
__device__ __forceinline__ uint32_t smem_u32(const void* p) {
    uint32_t a;
    asm("{ .reg .u64 t; cvta.to.shared.u64 t, %1; cvt.u32.u64 %0, t; }"
        : "=r"(a) : "l"(p));
    return a;
}
__device__ __forceinline__ unsigned ld_acq_gpu(const unsigned* p) {
    unsigned v;
    asm volatile("ld.acquire.gpu.global.u32 %0, [%1];" : "=r"(v) : "l"(p));
    return v;
}
__device__ __forceinline__ unsigned atom_add_acqrel(unsigned* p, unsigned v) {
    unsigned old;
    asm volatile("atom.acq_rel.gpu.global.add.u32 %0, [%1], %2;"
                 : "=r"(old) : "l"(p), "r"(v) : "memory");
    return old;
}
__device__ __forceinline__ float fast_tanh(float x) {
    float y; asm("tanh.approx.f32 %0, %1;" : "=f"(y) : "f"(x)); return y;
}
__device__ __forceinline__ float fast_sig(float x) {
    return fmaf(0.5f, fast_tanh(0.5f * x), 0.5f);
}
__device__ __forceinline__ void cp_async16(uint32_t dst, const void* src, int sz) {
    asm volatile("cp.async.cg.shared.global [%0], [%1], 16, %2;"
                 :: "r"(dst), "l"(src), "r"(sz) : "memory");
}
#define CP_COMMIT() asm volatile("cp.async.commit_group;" ::: "memory")
#define CP_WAIT1()  asm volatile("cp.async.wait_group 1;" ::: "memory")

#define LDSM4(r, addr)                                                        \
    asm volatile("ldmatrix.sync.aligned.m8n8.x4.shared.b16 {%0,%1,%2,%3}, [%4];" \
        : "=r"((r)[0]), "=r"((r)[1]), "=r"((r)[2]), "=r"((r)[3]) : "r"(addr))

#define MMA_BF16(c, a, b0, b1)                                                \
    asm volatile("mma.sync.aligned.m16n8k16.row.col.f32.bf16.bf16.f32 "       \
        "{%0,%1,%2,%3}, {%4,%5,%6,%7}, {%8,%9}, {%0,%1,%2,%3};"               \
        : "+f"((c)[0]), "+f"((c)[1]), "+f"((c)[2]), "+f"((c)[3])              \
        : "r"((a)[0]), "r"((a)[1]), "r"((a)[2]), "r"((a)[3]),                 \
          "r"(b0), "r"(b1))

// ===================== fp32 -> (bf16 hi, bf16 lo) convert ====================
__global__ void split_bf16_kernel(const float* __restrict__ x,
                                  __nv_bfloat16* __restrict__ hi,
                                  __nv_bfloat16* __restrict__ lo, int n)
{
    int i = blockIdx.x * blockDim.x + threadIdx.x;
    if (i < n) {
        const float v = x[i];
        const __nv_bfloat16 h = __float2bfloat16(v);
        hi[i] = h;
        lo[i] = __float2bfloat16(v - __bfloat162float(h));
    }
}

// ============ split-bf16 warp-MMA GEMM, cp.async double-buffered ============
// A:[M,K] (hi/lo bf16, M % 64 == 0), B:[N,K] (hi/lo bf16), K % 32 == 0.
// CTA tile 64x128, 8 warps as 2(m) x 4(n), warp tile 32x32, K chunk 32.
#define WBM 64
#define WBN 128
#define WKC 32
#define APITCH 80
#define OFF_AH 0
#define OFF_AL (OFF_AH + WBM * APITCH)      // 5120
#define OFF_BH (OFF_AL + WBM * APITCH)      // 10240
#define OFF_BL (OFF_BH + WBN * APITCH)      // 20480
#define BUF_SZ (OFF_BL + WBN * APITCH)      // 30720 per buffer

__global__ __launch_bounds__(256)
void bf16mma_gemm(const __nv_bfloat16* __restrict__ Ah,
                  const __nv_bfloat16* __restrict__ Al,
                  const __nv_bfloat16* __restrict__ Bh,
                  const __nv_bfloat16* __restrict__ Bl,
                  const float* __restrict__ b0, const float* __restrict__ b1,
                  float* __restrict__ C, int M, int N, int K)
{
    __shared__ __align__(128) char smem[2 * BUF_SZ];
    const uint32_t sbase = smem_u32(smem);

    const int tid  = threadIdx.x;
    const int lane = tid & 31;
    const int w    = tid >> 5;
    const int mrow = w & 1;
    const int ncol = w >> 1;
    const int m0   = blockIdx.y * WBM;
    const int n0   = blockIdx.x * WBN;

    float c[2][4][4];
#pragma unroll
    for (int i = 0; i < 2; ++i)
#pragma unroll
        for (int j = 0; j < 4; ++j)
#pragma unroll
            for (int q = 0; q < 4; ++q) c[i][j][q] = 0.f;

    const int ar = tid >> 2, aj = tid & 3;     // A row, 16B block
    const int br0 = tid >> 2, br1 = br0 + 64;  // B rows
    const int nn0 = n0 + br0, nn1 = n0 + br1;
    const int bsz0 = (nn0 < N) ? 16 : 0;
    const int bsz1 = (nn1 < N) ? 16 : 0;
    const size_t brow0 = (size_t)((nn0 < N) ? nn0 : 0) * K;  // clamped
    const size_t brow1 = (size_t)((nn1 < N) ? nn1 : 0) * K;
    const size_t arow_off = (size_t)(m0 + ar) * K;

    const int nch = K / WKC;

    // issue chunk `kb` into buffer `buf`
#define ISSUE(ch, buf)                                                        \
    {                                                                         \
        const int kb = (ch) * WKC;                                            \
        const uint32_t sb = sbase + (buf) * BUF_SZ;                           \
        const size_t ao = arow_off + kb + aj * 8;                             \
        cp_async16(sb + OFF_AH + ar * APITCH + aj * 16, Ah + ao, 16);         \
        cp_async16(sb + OFF_AL + ar * APITCH + aj * 16, Al + ao, 16);         \
        const size_t bo0 = brow0 + kb + aj * 8;                               \
        const size_t bo1 = brow1 + kb + aj * 8;                               \
        cp_async16(sb + OFF_BH + br0 * APITCH + aj * 16, Bh + bo0, bsz0);     \
        cp_async16(sb + OFF_BL + br0 * APITCH + aj * 16, Bl + bo0, bsz0);     \
        cp_async16(sb + OFF_BH + br1 * APITCH + aj * 16, Bh + bo1, bsz1);     \
        cp_async16(sb + OFF_BL + br1 * APITCH + aj * 16, Bl + bo1, bsz1);     \
    }
#define COMPUTE(buf)                                                          \
    {                                                                         \
        const uint32_t sb = sbase + (buf) * BUF_SZ;                           \
        _Pragma("unroll")                                                     \
        for (int ks = 0; ks < WKC; ks += 16) {                                \
            uint32_t ah[2][4], al[2][4], bh[2][4], bl[2][4];                  \
            _Pragma("unroll")                                                 \
            for (int mt = 0; mt < 2; ++mt) {                                  \
                const uint32_t arw = mrow * 32 + mt * 16 + (lane & 15);       \
                const uint32_t acl = (ks + (lane >> 4) * 8) * 2;              \
                LDSM4(ah[mt], sb + OFF_AH + arw * APITCH + acl);              \
                LDSM4(al[mt], sb + OFF_AL + arw * APITCH + acl);              \
            }                                                                 \
            _Pragma("unroll")                                                 \
            for (int p = 0; p < 2; ++p) {                                     \
                const uint32_t brw = ncol * 32 + p * 16 + (lane & 7)          \
                                     + ((lane >> 4) & 1) * 8;                 \
                const uint32_t bcl = (ks + ((lane >> 3) & 1) * 8) * 2;        \
                LDSM4(bh[p], sb + OFF_BH + brw * APITCH + bcl);               \
                LDSM4(bl[p], sb + OFF_BL + brw * APITCH + bcl);               \
            }                                                                 \
            _Pragma("unroll")                                                 \
            for (int mt = 0; mt < 2; ++mt)                                    \
                _Pragma("unroll")                                             \
                for (int nt = 0; nt < 4; ++nt) {                              \
                    const int p  = nt >> 1;                                   \
                    const int r0 = (nt & 1) * 2, r1 = r0 + 1;                 \
                    MMA_BF16(c[mt][nt], ah[mt], bh[p][r0], bh[p][r1]);        \
                    MMA_BF16(c[mt][nt], ah[mt], bl[p][r0], bl[p][r1]);        \
                    MMA_BF16(c[mt][nt], al[mt], bh[p][r0], bh[p][r1]);        \
                }                                                             \
        }                                                                     \
    }

    // ---- pipelined mainloop: depth-2 cp.async double buffer ----
    ISSUE(0, 0);
    CP_COMMIT();
    if (nch > 1) ISSUE(1, 1);
    CP_COMMIT();

    for (int ch = 0; ch < nch; ++ch) {
        CP_WAIT1();                 // chunk ch landed
        __syncthreads();
        COMPUTE(ch & 1);
        __syncthreads();            // all warps done reading buf ch&1
        if (ch + 2 < nch) ISSUE(ch + 2, ch & 1);
        CP_COMMIT();                // exactly one group per iteration
    }

    // ---- epilogue ----
#pragma unroll
    for (int mt = 0; mt < 2; ++mt) {
        const int mbase = m0 + mrow * 32 + mt * 16 + (lane >> 2);
#pragma unroll
        for (int nt = 0; nt < 4; ++nt) {
            const int n = n0 + ncol * 32 + nt * 8 + (lane & 3) * 2;
#pragma unroll
            for (int half = 0; half < 2; ++half) {
                const int m = mbase + half * 8;
                const float v0 = c[mt][nt][half * 2 + 0];
                const float v1 = c[mt][nt][half * 2 + 1];
                if (n < N) {
                    float v = v0;
                    if (b0) v += __ldg(&b0[n]);
                    if (b1) v += __ldg(&b1[n]);
                    C[(size_t)m * N + n] = v;
                }
                if (n + 1 < N) {
                    float v = v1;
                    if (b0) v += __ldg(&b0[n + 1]);
                    if (b1) v += __ldg(&b1[n + 1]);
                    C[(size_t)m * N + n + 1] = v;
                }
            }
        }
    }
#undef ISSUE
#undef COMPUTE
}

// =================== fp32 SGEMM (layer-0 xg, R11 verbatim) ==================
#define BM 64
#define BN 64
#define BK 16

__global__ __launch_bounds__(256)
void sgemm_nt_kernel(const float* __restrict__ A, const float* __restrict__ B,
                     const float* __restrict__ b0, const float* __restrict__ b1,
                     float* __restrict__ C, int M, int N, int K)
{
    __shared__ float As[BK][68];
    __shared__ float Bs[BK][68];

    const int tid = threadIdx.x;
    const int tx  = tid & 15;
    const int ty  = tid >> 4;
    const int lk  = tid & 15;
    const int lr  = tid >> 4;
    const int m0 = blockIdx.y * BM;
    const int n0 = blockIdx.x * BN;

    float acc[4][4];
#pragma unroll
    for (int i = 0; i < 4; ++i)
#pragma unroll
        for (int j = 0; j < 4; ++j) acc[i][j] = 0.f;

    for (int k0 = 0; k0 < K; k0 += BK) {
        const int k = k0 + lk;
        const bool kok = (k < K);
#pragma unroll
        for (int i = 0; i < 4; ++i) {
            const int m = m0 + lr + 16 * i;
            const int n = n0 + lr + 16 * i;
            As[lk][lr + 16 * i] = (kok && m < M) ? __ldg(&A[(size_t)m * K + k]) : 0.f;
            Bs[lk][lr + 16 * i] = (kok && n < N) ? __ldg(&B[(size_t)n * K + k]) : 0.f;
        }
        __syncthreads();
#pragma unroll
        for (int kk = 0; kk < BK; ++kk) {
            const float4 a = *(const float4*)&As[kk][ty * 4];
            const float4 b = *(const float4*)&Bs[kk][tx * 4];
            acc[0][0] = fmaf(a.x, b.x, acc[0][0]);
            acc[0][1] = fmaf(a.x, b.y, acc[0][1]);
            acc[0][2] = fmaf(a.x, b.z, acc[0][2]);
            acc[0][3] = fmaf(a.x, b.w, acc[0][3]);
            acc[1][0] = fmaf(a.y, b.x, acc[1][0]);
            acc[1][1] = fmaf(a.y, b.y, acc[1][1]);
            acc[1][2] = fmaf(a.y, b.z, acc[1][2]);
            acc[1][3] = fmaf(a.y, b.w, acc[1][3]);
            acc[2][0] = fmaf(a.z, b.x, acc[2][0]);
            acc[2][1] = fmaf(a.z, b.y, acc[2][1]);
            acc[2][2] = fmaf(a.z, b.z, acc[2][2]);
            acc[2][3] = fmaf(a.z, b.w, acc[2][3]);
            acc[3][0] = fmaf(a.w, b.x, acc[3][0]);
            acc[3][1] = fmaf(a.w, b.y, acc[3][1]);
            acc[3][2] = fmaf(a.w, b.z, acc[3][2]);
            acc[3][3] = fmaf(a.w, b.w, acc[3][3]);
        }
        __syncthreads();
    }

#pragma unroll
    for (int i = 0; i < 4; ++i) {
        const int m = m0 + ty * 4 + i;
        if (m >= M) continue;
#pragma unroll
        for (int j = 0; j < 4; ++j) {
            const int n = n0 + tx * 4 + j;
            if (n >= N) continue;
            float v = acc[i][j];
            if (b0) v += __ldg(&b0[n]);
            if (b1) v += __ldg(&b1[n]);
            C[(size_t)m * N + n] = v;
        }
    }
}

// =================== persistent LSTM recurrence (R11 verbatim) ==============
__global__ __launch_bounds__(NTHR_LSTM, 1)
void lstm_layer_kernel(const float* __restrict__ Whh,
                       const float* __restrict__ xg,
                       __nv_bfloat16* __restrict__ ah_out,
                       __nv_bfloat16* __restrict__ al_out)
{
    __shared__ float4 hs4[HID / 4];

    const int tid   = threadIdx.x;
    const int cta   = blockIdx.x;
    const int base  = cta * 8;
    const int lane  = tid & 31;
    const int warp  = tid >> 5;
    const int gate  = lane >> 3;
    const int lane8 = lane & 7;

    const float4* wsrc =
        (const float4*)(Whh + (size_t)(gate * HID + base + warp) * HID);
    float4 wr[32];
#pragma unroll
    for (int jj = 0; jj < 32; ++jj)
        wr[jj] = __ldg(&wsrc[lane8 + 8 * jj]);

    hs4[tid] = make_float4(0.f, 0.f, 0.f, 0.f);

    unsigned baseg = 0;
    if (warp == 0)
        baseg = ld_acq_gpu(&g_cnt1[lane * 32]) & ~2047u;

    const int gate_off = gate * HID + base + warp;
    float xgv = 0.f;
    if (lane8 == 0) xgv = __ldg(xg + gate_off);
    float c_reg = 0.f;
    __syncthreads();

    for (int t = 0; t < T_FRAMES; ++t) {
        float sum = 0.f;
#pragma unroll
        for (int jj = 0; jj < 32; ++jj) {
            const float4 h = hs4[lane8 + 8 * jj];
            sum = fmaf(wr[jj].x, h.x, sum);
            sum = fmaf(wr[jj].y, h.y, sum);
            sum = fmaf(wr[jj].z, h.z, sum);
            sum = fmaf(wr[jj].w, h.w, sum);
        }
        sum += __shfl_xor_sync(0xffffffffu, sum, 1);
        sum += __shfl_xor_sync(0xffffffffu, sum, 2);
        sum += __shfl_xor_sync(0xffffffffu, sum, 4);

        float act = 0.f;
        if (lane8 == 0) {
            const float a = sum + xgv;
            act = (gate == 2) ? fast_tanh(a) : fast_sig(a);
        }
        float xgn = 0.f;
        if (lane8 == 0 && t + 1 < T_FRAMES)
            xgn = __ldg(xg + (size_t)(t + 1) * GATES + gate_off);

        const float i_ = __shfl_sync(0xffffffffu, act, 0);
        const float f_ = __shfl_sync(0xffffffffu, act, 8);
        const float g_ = __shfl_sync(0xffffffffu, act, 16);
        const float o_ = __shfl_sync(0xffffffffu, act, 24);
        c_reg = f_ * c_reg + i_ * g_;
        const float h = o_ * fast_tanh(c_reg);
        if (lane == 0) {
            __stcg(((float*)g_h4) + base + warp, h);
            const __nv_bfloat16 hh = __float2bfloat16(h);
            ah_out[(size_t)t * HID + base + warp] = hh;
            al_out[(size_t)t * HID + base + warp] =
                __float2bfloat16(h - __bfloat162float(hh));
        }

        if (warp != 0) {
            asm volatile("bar.arrive 1, %0;" :: "r"(NTHR_LSTM) : "memory");
        } else {
            asm volatile("bar.sync 1, %0;" :: "r"(NTHR_LSTM) : "memory");
            if (lane == 0) {
                asm volatile("fence.acq_rel.gpu;" ::: "memory");
                atom_add_acqrel(&g_cnt1[(cta >> 2) * 32], 1u);
            }
            if (t < T_FRAMES - 1) {
                const unsigned tgt = baseg + 4u * (unsigned)(t + 1);
                bool ok;
                do {
                    ok = ((int)(ld_acq_gpu(&g_cnt1[lane * 32]) - tgt) >= 0);
                } while (!__all_sync(0xffffffffu, ok));
            }
        }

        if (t == T_FRAMES - 1) break;

        __syncthreads();
        hs4[tid] = __ldcg(((const float4*)g_h4) + tid);
        xgv = xgn;
        __syncthreads();
    }
}

// ================================ launch =====================================
extern "C" void kernel_launch(void* const* d_in, const int* in_sizes, int n_in,
                              void* d_out, int out_size)
{
    (void)in_sizes; (void)n_in; (void)out_size;

    const float* x       = (const float*)d_in[0];
    const float* W_ih[3] = {(const float*)d_in[1], (const float*)d_in[5], (const float*)d_in[9]};
    const float* W_hh[3] = {(const float*)d_in[2], (const float*)d_in[6], (const float*)d_in[10]};
    const float* b_ih[3] = {(const float*)d_in[3], (const float*)d_in[7], (const float*)d_in[11]};
    const float* b_hh[3] = {(const float*)d_in[4], (const float*)d_in[8], (const float*)d_in[12]};
    const float* W_out   = (const float*)d_in[13];
    float* out = (float*)d_out;

    float* xg;
    __nv_bfloat16 *wih_h, *wih_l, *wout_h, *wout_l, *a_h, *a_l;
    cudaGetSymbolAddress((void**)&xg,     g_xg);
    cudaGetSymbolAddress((void**)&wih_h,  g_wih_h);
    cudaGetSymbolAddress((void**)&wih_l,  g_wih_l);
    cudaGetSymbolAddress((void**)&wout_h, g_wout_h);
    cudaGetSymbolAddress((void**)&wout_l, g_wout_l);
    cudaGetSymbolAddress((void**)&a_h,    g_a_h);
    cudaGetSymbolAddress((void**)&a_l,    g_a_l);

    const dim3 blk256(256);
    const int  WIH_ELEMS  = GATES * HID;
    const int  WOUT_ELEMS = OUT_N * HID;

    // ---- weight conversions (pure functions of inputs) ----
    split_bf16_kernel<<<(WIH_ELEMS + 255) / 256, blk256>>>(W_ih[1], wih_h, wih_l, WIH_ELEMS);
    split_bf16_kernel<<<(WIH_ELEMS + 255) / 256, blk256>>>(W_ih[2], wih_h + WIH_ELEMS,
                                                           wih_l + WIH_ELEMS, WIH_ELEMS);
    split_bf16_kernel<<<(WOUT_ELEMS + 255) / 256, blk256>>>(W_out, wout_h, wout_l, WOUT_ELEMS);

    // ---- layer 0: fp32 xg GEMM (K=85) + recurrence ----
    const dim3 grid_xg0(GATES / BN, T_FRAMES / BM);            // (64, 8)
    sgemm_nt_kernel<<<grid_xg0, blk256>>>(x, W_ih[0], b_ih[0], b_hh[0], xg,
                                          T_FRAMES, GATES, IN_DIM);
    lstm_layer_kernel<<<NCTA_LSTM, blk256>>>(W_hh[0], xg, a_h, a_l);

    // ---- layer 1 ----
    const dim3 grid_xgt(GATES / WBN, T_FRAMES / WBM);          // (32, 8)
    bf16mma_gemm<<<grid_xgt, blk256>>>(a_h, a_l, wih_h, wih_l,
                                       b_ih[1], b_hh[1], xg,
                                       T_FRAMES, GATES, HID);
    lstm_layer_kernel<<<NCTA_LSTM, blk256>>>(W_hh[1], xg, a_h, a_l);

    // ---- layer 2 ----
    bf16mma_gemm<<<grid_xgt, blk256>>>(a_h, a_l, wih_h + WIH_ELEMS,
                                       wih_l + WIH_ELEMS,
                                       b_ih[2], b_hh[2], xg,
                                       T_FRAMES, GATES, HID);
    lstm_layer_kernel<<<NCTA_LSTM, blk256>>>(W_hh[2], xg, a_h, a_l);

    // ---- output projection ----
    const dim3 grid_out((OUT_N + WBN - 1) / WBN, T_FRAMES / WBM);  // (162, 8)
    bf16mma_gemm<<<grid_out, blk256>>>(a_h, a_l, wout_h, wout_l,
                                       nullptr, nullptr, out,
                                       T_FRAMES, OUT_N, HID);
}